// round 11
// baseline (speedup 1.0000x reference)
#include <cuda_runtime.h>
#include <cuda_fp16.h>
#include <cstdint>

#define B_ROWS 16384
#define NFEAT  2048
#define NINT   4096
#define NCLS   1000

#define BM 128
#define BN 128
#define BK 32
#define NKITER (NFEAT / BK)          // 64
#define NTILEC (NINT / BN)           // 32 column tiles
#define ROWB   80                    // padded smem row bytes (32 fp16 + 16B pad)
#define ASTAGE (BM * ROWB)           // 10240
#define STAGE_BYTES (2 * ASTAGE)     // 20480 (A then B)
#define STAGES 4
#define SMEM_DYN (STAGES * STAGE_BYTES)  // 81920
#define DELTA 0.05f                  // ~10 sigma of fp16-accum noise

// ---------------- scratch (device globals; no allocations) --------
__device__ __half g_xh [(size_t)B_ROWS * NFEAT];
__device__ __half g_w1h[(size_t)NINT   * NFEAT];
__device__ float g_t2v[(size_t)B_ROWS * NTILEC * 2];
__device__ int   g_t2i[(size_t)B_ROWS * NTILEC * 2];
__device__ int   g_amax[B_ROWS];
__device__ float g_w2t[(size_t)NINT * NCLS];

// ---------------- low-level helpers -------------------------------
__device__ __forceinline__ uint32_t smem_u32(const void* p) {
    uint32_t a;
    asm("{ .reg .u64 t; cvta.to.shared.u64 t, %1; cvt.u32.u64 %0, t; }" : "=r"(a) : "l"(p));
    return a;
}
__device__ __forceinline__ void cp_async16(uint32_t dst, const void* src) {
    asm volatile("cp.async.cg.shared.global [%0], [%1], 16;" :: "r"(dst), "l"(src));
}
#define CP_COMMIT() asm volatile("cp.async.commit_group;" ::: "memory")
#define CP_WAIT2()  asm volatile("cp.async.wait_group 2;"  ::: "memory")
#define CP_WAIT1()  asm volatile("cp.async.wait_group 1;"  ::: "memory")
#define CP_WAIT0()  asm volatile("cp.async.wait_group 0;"  ::: "memory")

__device__ __forceinline__ void ldsm4(uint32_t* r, uint32_t addr) {
    asm volatile("ldmatrix.sync.aligned.m8n8.x4.shared.b16 {%0,%1,%2,%3}, [%4];"
        : "=r"(r[0]), "=r"(r[1]), "=r"(r[2]), "=r"(r[3]) : "r"(addr));
}
// fp16 inputs, fp16 accumulate: D/C are 2 packed f16x2 regs
__device__ __forceinline__ void mma16816_f16(uint32_t* c, const uint32_t* a, const uint32_t* b) {
    asm volatile("mma.sync.aligned.m16n8k16.row.col.f16.f16.f16.f16 "
        "{%0,%1}, {%2,%3,%4,%5}, {%6,%7}, {%0,%1};"
        : "+r"(c[0]), "+r"(c[1])
        : "r"(a[0]), "r"(a[1]), "r"(a[2]), "r"(a[3]), "r"(b[0]), "r"(b[1]));
}
__device__ __forceinline__ void top2_merge(float& v1, int& i1, float& v2, int& i2,
                                           float v, int i) {
    if (v > v1 || (v == v1 && i < i1)) { v2 = v1; i2 = i1; v1 = v; i1 = i; }
    else if (v > v2 || (v == v2 && i < i2)) { v2 = v; i2 = i; }
}
// pinned fp32 fused FMA (matches Round-1 arithmetic exactly)
__device__ __forceinline__ void ffma_rn(float& s, float a, float b) {
    asm("fma.rn.f32 %0, %1, %2, %0;" : "+f"(s) : "f"(a), "f"(b));
}

// ---------------- fp32 -> fp16 conversion -------------------------
__global__ void __launch_bounds__(256)
cvt_kernel(const float4* __restrict__ x, const float4* __restrict__ w1)
{
    const size_t XT = (size_t)B_ROWS * NFEAT / 8;
    const size_t WT = (size_t)NINT * NFEAT / 8;
    size_t t = (size_t)blockIdx.x * 256 + threadIdx.x;
    const float4* src; uint4* dst; size_t u;
    if (t < XT)            { src = x;  dst = (uint4*)g_xh;  u = t; }
    else if (t < XT + WT)  { src = w1; dst = (uint4*)g_w1h; u = t - XT; }
    else return;
    float4 a = src[u * 2], b = src[u * 2 + 1];
    __half2 p0 = __floats2half2_rn(a.x, a.y);
    __half2 p1 = __floats2half2_rn(a.z, a.w);
    __half2 p2 = __floats2half2_rn(b.x, b.y);
    __half2 p3 = __floats2half2_rn(b.z, b.w);
    uint4 o;
    o.x = *(uint32_t*)&p0; o.y = *(uint32_t*)&p1;
    o.z = *(uint32_t*)&p2; o.w = *(uint32_t*)&p3;
    dst[u] = o;
}

// ---------------- stage loader (cp.async) -------------------------
__device__ __forceinline__ void load_stage(uint32_t st, int row0, int col0, int kt, int tid)
{
    int r  = tid >> 2;
    int kc = (tid & 3) * 8;                 // fp16 offset of 16B chunk
    uint32_t dA = st + r * ROWB + (tid & 3) * 16;
    cp_async16(dA,              &g_xh[(size_t)(row0 + r)      * NFEAT + kt + kc]);
    cp_async16(dA + 64 * ROWB,  &g_xh[(size_t)(row0 + r + 64) * NFEAT + kt + kc]);
    uint32_t dB = st + ASTAGE + r * ROWB + (tid & 3) * 16;
    cp_async16(dB,              &g_w1h[(size_t)(col0 + r)      * NFEAT + kt + kc]);
    cp_async16(dB + 64 * ROWB,  &g_w1h[(size_t)(col0 + r + 64) * NFEAT + kt + kc]);
}

// ---------------- HMMA fp16-acc GEMM + fused per-tile top-2 -------
__global__ void __launch_bounds__(256)
gemm_kernel(const float* __restrict__ b1)
{
    extern __shared__ char smem[];
    uint32_t tiles = smem_u32(smem);
    const int tid  = threadIdx.x;
    const int lane = tid & 31;
    const int w    = tid >> 5;
    const int wm   = w >> 2;          // 0..1  (64-row warp band)
    const int wn   = w & 3;           // 0..3  (32-col warp band)
    const int bx = blockIdx.x, by = blockIdx.y;
    const int row0 = by * BM, col0 = bx * BN;

    uint32_t acc[4][4][2];            // packed f16x2 accumulators
    #pragma unroll
    for (int mt = 0; mt < 4; ++mt)
        #pragma unroll
        for (int nt = 0; nt < 4; ++nt) { acc[mt][nt][0] = 0u; acc[mt][nt][1] = 0u; }

    // prologue: stages 0,1,2
    #pragma unroll
    for (int s = 0; s < 3; ++s) { load_stage(tiles + s * STAGE_BYTES, row0, col0, s * BK, tid); CP_COMMIT(); }

    // lane-invariant ldmatrix address components
    const uint32_t aOff = (wm * 64 + (lane & 15)) * ROWB + (lane >> 4) * 16;
    const uint32_t bOff = ASTAGE + (wn * 32 + ((lane & 7) + ((lane >> 4) << 3))) * ROWB
                        + ((lane >> 3) & 1) * 16;

    for (int j = 0; j < NKITER; ++j) {
        int rem = NKITER - 1 - j;
        if (rem >= 2)      { CP_WAIT2(); }
        else if (rem == 1) { CP_WAIT1(); }
        else               { CP_WAIT0(); }
        __syncthreads();
        if (j + 3 < NKITER) {
            load_stage(tiles + ((j + 3) & 3) * STAGE_BYTES, row0, col0, (j + 3) * BK, tid);
            CP_COMMIT();
        }
        uint32_t st = tiles + (j & 3) * STAGE_BYTES;
        uint32_t aB = st + aOff;
        uint32_t bB = st + bOff;
        #pragma unroll
        for (int kk = 0; kk < 2; ++kk) {
            uint32_t a[4][4], b[2][4];
            #pragma unroll
            for (int mt = 0; mt < 4; ++mt) ldsm4(a[mt], aB + mt * 16 * ROWB + kk * 32);
            #pragma unroll
            for (int p = 0; p < 2; ++p)    ldsm4(b[p], bB + p * 16 * ROWB + kk * 32);
            #pragma unroll
            for (int mt = 0; mt < 4; ++mt)
                #pragma unroll
                for (int nt = 0; nt < 4; ++nt)
                    mma16816_f16(acc[mt][nt], a[mt], &b[nt >> 1][(nt & 1) * 2]);
        }
    }

    // ---- epilogue: +b1, per-row top-2 over this 128-col tile ----
    float bv[8];
    #pragma unroll
    for (int nt = 0; nt < 4; ++nt) {
        int c = col0 + wn * 32 + nt * 8 + (lane & 3) * 2;
        bv[nt * 2]     = __ldg(&b1[c]);
        bv[nt * 2 + 1] = __ldg(&b1[c + 1]);
    }
    float* sv = (float*)smem;                       // [128][4][2]
    int*   si = (int*)(smem + 4096);                // [128][4][2]

    #pragma unroll
    for (int mt = 0; mt < 4; ++mt)
        #pragma unroll
        for (int h = 0; h < 2; ++h) {               // h=0: {c0,c1} row r; h=1: {c2,c3} row r+8
            float v1 = -3e38f, v2 = -3e38f;
            int   i1 = 0x7fffffff, i2 = 0x7fffffff;
            #pragma unroll
            for (int nt = 0; nt < 4; ++nt) {
                float2 p = __half22float2(*(__half2*)&acc[mt][nt][h]);
                #pragma unroll
                for (int e = 0; e < 2; ++e) {
                    float v = (e ? p.y : p.x) + bv[nt * 2 + e];
                    int col = col0 + wn * 32 + nt * 8 + (lane & 3) * 2 + e;
                    top2_merge(v1, i1, v2, i2, v, col);
                }
            }
            #pragma unroll
            for (int off = 1; off <= 2; off <<= 1) {
                float ov1 = __shfl_xor_sync(~0u, v1, off);
                int   oi1 = __shfl_xor_sync(~0u, i1, off);
                float ov2 = __shfl_xor_sync(~0u, v2, off);
                int   oi2 = __shfl_xor_sync(~0u, i2, off);
                top2_merge(v1, i1, v2, i2, ov1, oi1);
                top2_merge(v1, i1, v2, i2, ov2, oi2);
            }
            if ((lane & 3) == 0) {
                int rl = wm * 64 + mt * 16 + h * 8 + (lane >> 2);
                sv[(rl * 4 + wn) * 2]     = v1;
                sv[(rl * 4 + wn) * 2 + 1] = v2;
                si[(rl * 4 + wn) * 2]     = i1;
                si[(rl * 4 + wn) * 2 + 1] = i2;
            }
        }
    __syncthreads();
    if (tid < 128) {
        float v1 = -3e38f, v2 = -3e38f;
        int   i1 = 0x7fffffff, i2 = 0x7fffffff;
        #pragma unroll
        for (int k = 0; k < 8; ++k)
            top2_merge(v1, i1, v2, i2, sv[tid * 8 + k], si[tid * 8 + k]);
        size_t o = (size_t)(row0 + tid) * (NTILEC * 2) + bx * 2;
        g_t2v[o] = v1; g_t2i[o] = i1;
        g_t2v[o + 1] = v2; g_t2i[o + 1] = i2;
    }
}

// ---------------- exact refinement: sequential fp32 FMA chain -----
__global__ void __launch_bounds__(256)
refine_kernel(const float* __restrict__ x, const float* __restrict__ w1,
              const float* __restrict__ b1)
{
    __shared__ int s_cand[8][32];
    const int w = threadIdx.x >> 5, lane = threadIdx.x & 31;
    const int row = blockIdx.x * 8 + w;

    float v0 = g_t2v[(size_t)row * 64 + lane];
    float v1 = g_t2v[(size_t)row * 64 + 32 + lane];
    int   c0 = g_t2i[(size_t)row * 64 + lane];
    int   c1 = g_t2i[(size_t)row * 64 + 32 + lane];
    float m = fmaxf(v0, v1);
    #pragma unroll
    for (int o = 16; o; o >>= 1) m = fmaxf(m, __shfl_xor_sync(~0u, m, o));
    unsigned mask0 = __ballot_sync(~0u, v0 >= m - DELTA);
    unsigned mask1 = __ballot_sync(~0u, v1 >= m - DELTA);
    int n0 = __popc(mask0);
    int nc = n0 + __popc(mask1);
    if (nc > 32) nc = 32;
    if ((mask0 >> lane) & 1)
        s_cand[w][__popc(mask0 & ((1u << lane) - 1))] = c0;
    if ((mask1 >> lane) & 1) {
        int sl = n0 + __popc(mask1 & ((1u << lane) - 1));
        if (sl < 32) s_cand[w][sl] = c1;
    }
    __syncwarp();

    const bool act = lane < nc;
    int j = s_cand[w][act ? lane : 0];
    const float* xr = x + (size_t)row * NFEAT;
    const float* wr = w1 + (size_t)j * NFEAT;

    float s = 0.f;
    #pragma unroll 4
    for (int k = 0; k < NFEAT; k += 8) {
        float4 xa = *(const float4*)&xr[k];
        float4 xb = *(const float4*)&xr[k + 4];
        float4 wa = *(const float4*)&wr[k];
        float4 wb = *(const float4*)&wr[k + 4];
        ffma_rn(s, xa.x, wa.x); ffma_rn(s, xa.y, wa.y);
        ffma_rn(s, xa.z, wa.z); ffma_rn(s, xa.w, wa.w);
        ffma_rn(s, xb.x, wb.x); ffma_rn(s, xb.y, wb.y);
        ffma_rn(s, xb.z, wb.z); ffma_rn(s, xb.w, wb.w);
    }
    float bb = __ldg(&b1[j]);
    asm("add.rn.f32 %0, %0, %1;" : "+f"(s) : "f"(bb));

    if (!act) { s = -3e38f; j = 0x7fffffff; }
    #pragma unroll
    for (int o = 16; o; o >>= 1) {
        float os = __shfl_xor_sync(~0u, s, o);
        int   oj = __shfl_xor_sync(~0u, j, o);
        if (os > s || (os == s && oj < j)) { s = os; j = oj; }
    }
    if (lane == 0) g_amax[row] = j;
}

// ---------------- transpose w2 [1000,4096] -> [4096,1000] ---------
__global__ void transpose_kernel(const float* __restrict__ w2)
{
    __shared__ float tile[32][33];
    const int bx = blockIdx.x, by = blockIdx.y;
    const int tx = threadIdx.x, ty = threadIdx.y;
    const int c = bx * 32 + tx;
    #pragma unroll
    for (int j = 0; j < 32; j += 8) {
        int r = by * 32 + ty + j;
        if (r < NCLS) tile[ty + j][tx] = w2[(size_t)r * NINT + c];
    }
    __syncthreads();
    const int oc = by * 32 + tx;
    #pragma unroll
    for (int j = 0; j < 32; j += 8) {
        int orow = bx * 32 + ty + j;
        if (oc < NCLS) g_w2t[(size_t)orow * NCLS + oc] = tile[tx][ty + j];
    }
}

// ---------------- gather: out[b,:] = w2t[idx[b],:] + b2 -----------
__global__ void gather_kernel(const float* __restrict__ b2, float* __restrict__ out)
{
    const int b = blockIdx.x;
    const int idx = g_amax[b];
    const float4* src = (const float4*)&g_w2t[(size_t)idx * NCLS];
    const float4* bb  = (const float4*)b2;
    float4* dst = (float4*)&out[(size_t)b * NCLS];
    const int t = threadIdx.x;
    if (t < NCLS / 4) {
        float4 v = src[t], w = bb[t];
        v.x += w.x; v.y += w.y; v.z += w.z; v.w += w.w;
        dst[t] = v;
    }
}

// ------------------------------------------------------------------
extern "C" void kernel_launch(void* const* d_in, const int* in_sizes, int n_in,
                              void* d_out, int out_size)
{
    const float* x  = (const float*)d_in[0];
    const float* w1 = (const float*)d_in[1];
    const float* b1 = (const float*)d_in[2];
    const float* w2 = (const float*)d_in[3];
    const float* b2 = (const float*)d_in[4];
    float* out = (float*)d_out;

    cudaFuncSetAttribute(gemm_kernel, cudaFuncAttributeMaxDynamicSharedMemorySize, SMEM_DYN);

    const int cvt_blocks = (int)(((size_t)B_ROWS * NFEAT / 8 + (size_t)NINT * NFEAT / 8 + 255) / 256);
    cvt_kernel<<<cvt_blocks, 256>>>((const float4*)x, (const float4*)w1);
    gemm_kernel<<<dim3(NTILEC, B_ROWS / BM), 256, SMEM_DYN>>>(b1);
    refine_kernel<<<B_ROWS / 8, 256>>>(x, w1, b1);
    transpose_kernel<<<dim3(NINT / 32, (NCLS + 31) / 32), dim3(32, 8)>>>(w2);
    gather_kernel<<<B_ROWS, 256>>>(b2, out);
}

// round 16
// speedup vs baseline: 1.7503x; 1.7503x over previous
#include <cuda_runtime.h>
#include <cuda_bf16.h>
#include <cstdint>

#define B_ROWS 16384
#define NFEAT  2048
#define NINT   4096
#define NCLS   1000

#define BM 128
#define BN 128
#define BK 32
#define NKITER (NFEAT / BK)          // 64
#define NTILEC (NINT / BN)           // 32 column tiles
#define ROWB   80                    // padded smem row bytes (32 bf16 + 16B pad)
#define ASTAGE (BM * ROWB)           // 10240
#define STAGE_BYTES (2 * ASTAGE)     // 20480 (A then B)
#define STAGES 4
#define SMEM_DYN (STAGES * STAGE_BYTES)  // 81920
#define DELTA 0.03f

// ---------------- scratch (device globals; no allocations) --------
__device__ __nv_bfloat16 g_xb [(size_t)B_ROWS * NFEAT];
__device__ __nv_bfloat16 g_w1b[(size_t)NINT   * NFEAT];
__device__ float g_t2v[(size_t)B_ROWS * NTILEC * 2];
__device__ int   g_t2i[(size_t)B_ROWS * NTILEC * 2];
__device__ int   g_amax[B_ROWS];
__device__ float g_w2t[(size_t)NINT * NCLS];

// ---------------- low-level helpers -------------------------------
__device__ __forceinline__ uint32_t smem_u32(const void* p) {
    uint32_t a;
    asm("{ .reg .u64 t; cvta.to.shared.u64 t, %1; cvt.u32.u64 %0, t; }" : "=r"(a) : "l"(p));
    return a;
}
__device__ __forceinline__ void cp_async16(uint32_t dst, const void* src) {
    asm volatile("cp.async.cg.shared.global [%0], [%1], 16;" :: "r"(dst), "l"(src));
}
#define CP_COMMIT() asm volatile("cp.async.commit_group;" ::: "memory")
#define CP_WAIT2()  asm volatile("cp.async.wait_group 2;"  ::: "memory")
#define CP_WAIT1()  asm volatile("cp.async.wait_group 1;"  ::: "memory")
#define CP_WAIT0()  asm volatile("cp.async.wait_group 0;"  ::: "memory")

__device__ __forceinline__ void ldsm4(uint32_t* r, uint32_t addr) {
    asm volatile("ldmatrix.sync.aligned.m8n8.x4.shared.b16 {%0,%1,%2,%3}, [%4];"
        : "=r"(r[0]), "=r"(r[1]), "=r"(r[2]), "=r"(r[3]) : "r"(addr));
}
__device__ __forceinline__ void mma16816(float* c, const uint32_t* a, const uint32_t* b) {
    asm volatile("mma.sync.aligned.m16n8k16.row.col.f32.bf16.bf16.f32 "
        "{%0,%1,%2,%3}, {%4,%5,%6,%7}, {%8,%9}, {%0,%1,%2,%3};"
        : "+f"(c[0]), "+f"(c[1]), "+f"(c[2]), "+f"(c[3])
        : "r"(a[0]), "r"(a[1]), "r"(a[2]), "r"(a[3]), "r"(b[0]), "r"(b[1]));
}
__device__ __forceinline__ void top2_merge(float& v1, int& i1, float& v2, int& i2,
                                           float v, int i) {
    if (v > v1 || (v == v1 && i < i1)) { v2 = v1; i2 = i1; v1 = v; i1 = i; }
    else if (v > v2 || (v == v2 && i < i2)) { v2 = v; i2 = i; }
}
// pinned fp32 fused FMA (matches Round-1 arithmetic exactly)
__device__ __forceinline__ void ffma_rn(float& s, float a, float b) {
    asm("fma.rn.f32 %0, %1, %2, %0;" : "+f"(s) : "f"(a), "f"(b));
}

// ---------------- fp32 -> bf16 conversion -------------------------
__global__ void __launch_bounds__(256)
cvt_kernel(const float4* __restrict__ x, const float4* __restrict__ w1)
{
    const size_t XT = (size_t)B_ROWS * NFEAT / 8;
    const size_t WT = (size_t)NINT * NFEAT / 8;
    size_t t = (size_t)blockIdx.x * 256 + threadIdx.x;
    const float4* src; uint4* dst; size_t u;
    if (t < XT)            { src = x;  dst = (uint4*)g_xb;  u = t; }
    else if (t < XT + WT)  { src = w1; dst = (uint4*)g_w1b; u = t - XT; }
    else return;
    float4 a = src[u * 2], b = src[u * 2 + 1];
    __nv_bfloat162 p0 = __floats2bfloat162_rn(a.x, a.y);
    __nv_bfloat162 p1 = __floats2bfloat162_rn(a.z, a.w);
    __nv_bfloat162 p2 = __floats2bfloat162_rn(b.x, b.y);
    __nv_bfloat162 p3 = __floats2bfloat162_rn(b.z, b.w);
    uint4 o;
    o.x = *(uint32_t*)&p0; o.y = *(uint32_t*)&p1;
    o.z = *(uint32_t*)&p2; o.w = *(uint32_t*)&p3;
    dst[u] = o;
}

// ---------------- stage loader (cp.async) -------------------------
__device__ __forceinline__ void load_stage(uint32_t st, int row0, int col0, int kt, int tid)
{
    int r  = tid >> 2;
    int kc = (tid & 3) * 8;                 // bf16 offset of 16B chunk
    uint32_t dA = st + r * ROWB + (tid & 3) * 16;
    cp_async16(dA,              &g_xb[(size_t)(row0 + r)      * NFEAT + kt + kc]);
    cp_async16(dA + 64 * ROWB,  &g_xb[(size_t)(row0 + r + 64) * NFEAT + kt + kc]);
    uint32_t dB = st + ASTAGE + r * ROWB + (tid & 3) * 16;
    cp_async16(dB,              &g_w1b[(size_t)(col0 + r)      * NFEAT + kt + kc]);
    cp_async16(dB + 64 * ROWB,  &g_w1b[(size_t)(col0 + r + 64) * NFEAT + kt + kc]);
}

// ---------------- HMMA bf16 GEMM + fused per-tile top-2 -----------
__global__ void __launch_bounds__(256)
gemm_kernel(const float* __restrict__ b1)
{
    extern __shared__ char smem[];
    uint32_t tiles = smem_u32(smem);
    const int tid  = threadIdx.x;
    const int lane = tid & 31;
    const int w    = tid >> 5;
    const int wm   = w >> 2;          // 0..1  (64-row warp band)
    const int wn   = w & 3;           // 0..3  (32-col warp band)
    const int bx = blockIdx.x, by = blockIdx.y;
    const int row0 = by * BM, col0 = bx * BN;

    float acc[4][4][4];
    #pragma unroll
    for (int mt = 0; mt < 4; ++mt)
        #pragma unroll
        for (int nt = 0; nt < 4; ++nt)
            #pragma unroll
            for (int v = 0; v < 4; ++v) acc[mt][nt][v] = 0.f;

    // prologue: stages 0,1,2
    #pragma unroll
    for (int s = 0; s < 3; ++s) { load_stage(tiles + s * STAGE_BYTES, row0, col0, s * BK, tid); CP_COMMIT(); }

    // lane-invariant ldmatrix address components
    const uint32_t aOff = (wm * 64 + (lane & 15)) * ROWB + (lane >> 4) * 16;
    const uint32_t bOff = ASTAGE + (wn * 32 + ((lane & 7) + ((lane >> 4) << 3))) * ROWB
                        + ((lane >> 3) & 1) * 16;

    for (int j = 0; j < NKITER; ++j) {
        int rem = NKITER - 1 - j;
        if (rem >= 2)      { CP_WAIT2(); }
        else if (rem == 1) { CP_WAIT1(); }
        else               { CP_WAIT0(); }
        __syncthreads();                    // single barrier per iteration
        if (j + 3 < NKITER) {
            load_stage(tiles + ((j + 3) & 3) * STAGE_BYTES, row0, col0, (j + 3) * BK, tid);
            CP_COMMIT();
        }
        uint32_t st = tiles + (j & 3) * STAGE_BYTES;
        uint32_t aB = st + aOff;
        uint32_t bB = st + bOff;
        #pragma unroll
        for (int kk = 0; kk < 2; ++kk) {
            uint32_t a[4][4], b[2][4];
            #pragma unroll
            for (int mt = 0; mt < 4; ++mt) ldsm4(a[mt], aB + mt * 16 * ROWB + kk * 32);
            #pragma unroll
            for (int p = 0; p < 2; ++p)    ldsm4(b[p], bB + p * 16 * ROWB + kk * 32);
            #pragma unroll
            for (int mt = 0; mt < 4; ++mt)
                #pragma unroll
                for (int nt = 0; nt < 4; ++nt)
                    mma16816(acc[mt][nt], a[mt], &b[nt >> 1][(nt & 1) * 2]);
        }
    }

    // ---- epilogue: +b1, per-row top-2 over this 128-col tile ----
    float bv[8];
    #pragma unroll
    for (int nt = 0; nt < 4; ++nt) {
        int c = col0 + wn * 32 + nt * 8 + (lane & 3) * 2;
        bv[nt * 2]     = __ldg(&b1[c]);
        bv[nt * 2 + 1] = __ldg(&b1[c + 1]);
    }
    float* sv = (float*)smem;                       // [128][4][2]
    int*   si = (int*)(smem + 4096);                // [128][4][2]

    #pragma unroll
    for (int mt = 0; mt < 4; ++mt)
        #pragma unroll
        for (int h = 0; h < 2; ++h) {
            float v1 = -3e38f, v2 = -3e38f;
            int   i1 = 0x7fffffff, i2 = 0x7fffffff;
            #pragma unroll
            for (int nt = 0; nt < 4; ++nt)
                #pragma unroll
                for (int e = 0; e < 2; ++e) {
                    float v = acc[mt][nt][h * 2 + e] + bv[nt * 2 + e];
                    int col = col0 + wn * 32 + nt * 8 + (lane & 3) * 2 + e;
                    top2_merge(v1, i1, v2, i2, v, col);
                }
            #pragma unroll
            for (int off = 1; off <= 2; off <<= 1) {
                float ov1 = __shfl_xor_sync(~0u, v1, off);
                int   oi1 = __shfl_xor_sync(~0u, i1, off);
                float ov2 = __shfl_xor_sync(~0u, v2, off);
                int   oi2 = __shfl_xor_sync(~0u, i2, off);
                top2_merge(v1, i1, v2, i2, ov1, oi1);
                top2_merge(v1, i1, v2, i2, ov2, oi2);
            }
            if ((lane & 3) == 0) {
                int rl = wm * 64 + mt * 16 + h * 8 + (lane >> 2);
                sv[(rl * 4 + wn) * 2]     = v1;
                sv[(rl * 4 + wn) * 2 + 1] = v2;
                si[(rl * 4 + wn) * 2]     = i1;
                si[(rl * 4 + wn) * 2 + 1] = i2;
            }
        }
    __syncthreads();
    if (tid < 128) {
        float v1 = -3e38f, v2 = -3e38f;
        int   i1 = 0x7fffffff, i2 = 0x7fffffff;
        #pragma unroll
        for (int k = 0; k < 8; ++k)
            top2_merge(v1, i1, v2, i2, sv[tid * 8 + k], si[tid * 8 + k]);
        size_t o = (size_t)(row0 + tid) * (NTILEC * 2) + bx * 2;
        g_t2v[o] = v1; g_t2i[o] = i1;
        g_t2v[o + 1] = v2; g_t2i[o + 1] = i2;
    }
}

// ---------------- exact refinement: sequential fp32 FMA chain -----
// Fast path: if only ONE column lies within DELTA of the bf16 max, the
// bf16 top-1 is provably the fp32 argmax (any fp32 winner must sit within
// GEMM noise << DELTA of the bf16 max, hence be a candidate) -> skip the
// dot-product chain entirely (~87% of rows).
__global__ void __launch_bounds__(256)
refine_kernel(const float* __restrict__ x, const float* __restrict__ w1,
              const float* __restrict__ b1)
{
    __shared__ int s_cand[8][32];
    const int w = threadIdx.x >> 5, lane = threadIdx.x & 31;
    const int row = blockIdx.x * 8 + w;

    float v0 = g_t2v[(size_t)row * 64 + lane];
    float v1 = g_t2v[(size_t)row * 64 + 32 + lane];
    int   c0 = g_t2i[(size_t)row * 64 + lane];
    int   c1 = g_t2i[(size_t)row * 64 + 32 + lane];
    float m = fmaxf(v0, v1);
    #pragma unroll
    for (int o = 16; o; o >>= 1) m = fmaxf(m, __shfl_xor_sync(~0u, m, o));
    unsigned mask0 = __ballot_sync(~0u, v0 >= m - DELTA);
    unsigned mask1 = __ballot_sync(~0u, v1 >= m - DELTA);
    int n0 = __popc(mask0);
    int nc = n0 + __popc(mask1);
    if (nc > 32) nc = 32;
    if ((mask0 >> lane) & 1)
        s_cand[w][__popc(mask0 & ((1u << lane) - 1))] = c0;
    if ((mask1 >> lane) & 1) {
        int sl = n0 + __popc(mask1 & ((1u << lane) - 1));
        if (sl < 32) s_cand[w][sl] = c1;
    }
    __syncwarp();

    if (nc == 1) {                      // unique candidate == argmax; no chain
        if (lane == 0) g_amax[row] = s_cand[w][0];
        return;
    }

    const bool act = lane < nc;
    int j = s_cand[w][act ? lane : 0];
    const float* xr = x + (size_t)row * NFEAT;
    const float* wr = w1 + (size_t)j * NFEAT;

    float s = 0.f;
    #pragma unroll 4
    for (int k = 0; k < NFEAT; k += 8) {
        float4 xa = *(const float4*)&xr[k];
        float4 xb = *(const float4*)&xr[k + 4];
        float4 wa = *(const float4*)&wr[k];
        float4 wb = *(const float4*)&wr[k + 4];
        ffma_rn(s, xa.x, wa.x); ffma_rn(s, xa.y, wa.y);
        ffma_rn(s, xa.z, wa.z); ffma_rn(s, xa.w, wa.w);
        ffma_rn(s, xb.x, wb.x); ffma_rn(s, xb.y, wb.y);
        ffma_rn(s, xb.z, wb.z); ffma_rn(s, xb.w, wb.w);
    }
    float bb = __ldg(&b1[j]);
    asm("add.rn.f32 %0, %0, %1;" : "+f"(s) : "f"(bb));

    if (!act) { s = -3e38f; j = 0x7fffffff; }
    #pragma unroll
    for (int o = 16; o; o >>= 1) {
        float os = __shfl_xor_sync(~0u, s, o);
        int   oj = __shfl_xor_sync(~0u, j, o);
        if (os > s || (os == s && oj < j)) { s = os; j = oj; }
    }
    if (lane == 0) g_amax[row] = j;
}

// ---------------- transpose w2 [1000,4096] -> [4096,1000] ---------
__global__ void transpose_kernel(const float* __restrict__ w2)
{
    __shared__ float tile[32][33];
    const int bx = blockIdx.x, by = blockIdx.y;
    const int tx = threadIdx.x, ty = threadIdx.y;
    const int c = bx * 32 + tx;
    #pragma unroll
    for (int j = 0; j < 32; j += 8) {
        int r = by * 32 + ty + j;
        if (r < NCLS) tile[ty + j][tx] = w2[(size_t)r * NINT + c];
    }
    __syncthreads();
    const int oc = by * 32 + tx;
    #pragma unroll
    for (int j = 0; j < 32; j += 8) {
        int orow = bx * 32 + ty + j;
        if (oc < NCLS) g_w2t[(size_t)orow * NCLS + oc] = tile[tx][ty + j];
    }
}

// ---------------- gather: out[b,:] = w2t[idx[b],:] + b2 -----------
__global__ void gather_kernel(const float* __restrict__ b2, float* __restrict__ out)
{
    const int b = blockIdx.x;
    const int idx = g_amax[b];
    const float4* src = (const float4*)&g_w2t[(size_t)idx * NCLS];
    const float4* bb  = (const float4*)b2;
    float4* dst = (float4*)&out[(size_t)b * NCLS];
    const int t = threadIdx.x;
    if (t < NCLS / 4) {
        float4 v = src[t], w = bb[t];
        v.x += w.x; v.y += w.y; v.z += w.z; v.w += w.w;
        dst[t] = v;
    }
}

// ------------------------------------------------------------------
extern "C" void kernel_launch(void* const* d_in, const int* in_sizes, int n_in,
                              void* d_out, int out_size)
{
    const float* x  = (const float*)d_in[0];
    const float* w1 = (const float*)d_in[1];
    const float* b1 = (const float*)d_in[2];
    const float* w2 = (const float*)d_in[3];
    const float* b2 = (const float*)d_in[4];
    float* out = (float*)d_out;

    cudaFuncSetAttribute(gemm_kernel, cudaFuncAttributeMaxDynamicSharedMemorySize, SMEM_DYN);

    const int cvt_blocks = (int)(((size_t)B_ROWS * NFEAT / 8 + (size_t)NINT * NFEAT / 8 + 255) / 256);
    cvt_kernel<<<cvt_blocks, 256>>>((const float4*)x, (const float4*)w1);
    gemm_kernel<<<dim3(NTILEC, B_ROWS / BM), 256, SMEM_DYN>>>(b1);
    refine_kernel<<<B_ROWS / 8, 256>>>(x, w1, b1);
    transpose_kernel<<<dim3(NINT / 32, (NCLS + 31) / 32), dim3(32, 8)>>>(w2);
    gather_kernel<<<B_ROWS, 256>>>(b2, out);
}

// round 17
// speedup vs baseline: 1.8426x; 1.0527x over previous
#include <cuda_runtime.h>
#include <cuda_bf16.h>
#include <cstdint>

#define B_ROWS 16384
#define NFEAT  2048
#define NINT   4096
#define NCLS   1000

#define BM 128
#define BN 128
#define BK 32
#define NKITER (NFEAT / BK)          // 64
#define NTILEC (NINT / BN)           // 32 column tiles
#define ROWB   80                    // padded smem row bytes (32 bf16 + 16B pad)
#define ASTAGE (BM * ROWB)           // 10240
#define STAGE_BYTES (2 * ASTAGE)     // 20480 (A then B)
#define STAGES 3
#define SMEM_DYN (STAGES * STAGE_BYTES)  // 61440 -> 2 CTAs/SM
#define DELTA 0.03f

// ---------------- scratch (device globals; no allocations) --------
__device__ __nv_bfloat16 g_xb [(size_t)B_ROWS * NFEAT];
__device__ __nv_bfloat16 g_w1b[(size_t)NINT   * NFEAT];
__device__ float g_t2v[(size_t)B_ROWS * NTILEC * 2];
__device__ int   g_t2i[(size_t)B_ROWS * NTILEC * 2];
__device__ int   g_amax[B_ROWS];
__device__ float g_w2t[(size_t)NINT * NCLS];

// ---------------- low-level helpers -------------------------------
__device__ __forceinline__ uint32_t smem_u32(const void* p) {
    uint32_t a;
    asm("{ .reg .u64 t; cvta.to.shared.u64 t, %1; cvt.u32.u64 %0, t; }" : "=r"(a) : "l"(p));
    return a;
}
__device__ __forceinline__ void cp_async16(uint32_t dst, const void* src) {
    asm volatile("cp.async.cg.shared.global [%0], [%1], 16;" :: "r"(dst), "l"(src));
}
#define CP_COMMIT() asm volatile("cp.async.commit_group;" ::: "memory")
#define CP_WAIT1()  asm volatile("cp.async.wait_group 1;"  ::: "memory")
#define CP_WAIT0()  asm volatile("cp.async.wait_group 0;"  ::: "memory")

__device__ __forceinline__ void ldsm4(uint32_t* r, uint32_t addr) {
    asm volatile("ldmatrix.sync.aligned.m8n8.x4.shared.b16 {%0,%1,%2,%3}, [%4];"
        : "=r"(r[0]), "=r"(r[1]), "=r"(r[2]), "=r"(r[3]) : "r"(addr));
}
__device__ __forceinline__ void mma16816(float* c, const uint32_t* a, const uint32_t* b) {
    asm volatile("mma.sync.aligned.m16n8k16.row.col.f32.bf16.bf16.f32 "
        "{%0,%1,%2,%3}, {%4,%5,%6,%7}, {%8,%9}, {%0,%1,%2,%3};"
        : "+f"(c[0]), "+f"(c[1]), "+f"(c[2]), "+f"(c[3])
        : "r"(a[0]), "r"(a[1]), "r"(a[2]), "r"(a[3]), "r"(b[0]), "r"(b[1]));
}
__device__ __forceinline__ void top2_merge(float& v1, int& i1, float& v2, int& i2,
                                           float v, int i) {
    if (v > v1 || (v == v1 && i < i1)) { v2 = v1; i2 = i1; v1 = v; i1 = i; }
    else if (v > v2 || (v == v2 && i < i2)) { v2 = v; i2 = i; }
}
// pinned fp32 fused FMA (matches Round-1 arithmetic exactly)
__device__ __forceinline__ void ffma_rn(float& s, float a, float b) {
    asm("fma.rn.f32 %0, %1, %2, %0;" : "+f"(s) : "f"(a), "f"(b));
}

// ---------------- fp32 -> bf16 conversion -------------------------
__global__ void __launch_bounds__(256)
cvt_kernel(const float4* __restrict__ x, const float4* __restrict__ w1)
{
    const size_t XT = (size_t)B_ROWS * NFEAT / 8;
    const size_t WT = (size_t)NINT * NFEAT / 8;
    size_t t = (size_t)blockIdx.x * 256 + threadIdx.x;
    const float4* src; uint4* dst; size_t u;
    if (t < XT)            { src = x;  dst = (uint4*)g_xb;  u = t; }
    else if (t < XT + WT)  { src = w1; dst = (uint4*)g_w1b; u = t - XT; }
    else return;
    float4 a = src[u * 2], b = src[u * 2 + 1];
    __nv_bfloat162 p0 = __floats2bfloat162_rn(a.x, a.y);
    __nv_bfloat162 p1 = __floats2bfloat162_rn(a.z, a.w);
    __nv_bfloat162 p2 = __floats2bfloat162_rn(b.x, b.y);
    __nv_bfloat162 p3 = __floats2bfloat162_rn(b.z, b.w);
    uint4 o;
    o.x = *(uint32_t*)&p0; o.y = *(uint32_t*)&p1;
    o.z = *(uint32_t*)&p2; o.w = *(uint32_t*)&p3;
    dst[u] = o;
}

// ---------------- stage loader (cp.async) -------------------------
__device__ __forceinline__ void load_stage(uint32_t st, int row0, int col0, int kt, int tid)
{
    int r  = tid >> 2;
    int kc = (tid & 3) * 8;                 // bf16 offset of 16B chunk
    uint32_t dA = st + r * ROWB + (tid & 3) * 16;
    cp_async16(dA,              &g_xb[(size_t)(row0 + r)      * NFEAT + kt + kc]);
    cp_async16(dA + 64 * ROWB,  &g_xb[(size_t)(row0 + r + 64) * NFEAT + kt + kc]);
    uint32_t dB = st + ASTAGE + r * ROWB + (tid & 3) * 16;
    cp_async16(dB,              &g_w1b[(size_t)(col0 + r)      * NFEAT + kt + kc]);
    cp_async16(dB + 64 * ROWB,  &g_w1b[(size_t)(col0 + r + 64) * NFEAT + kt + kc]);
}

// ---------------- HMMA bf16 GEMM + fused per-tile top-2 -----------
// 3 stages / 60 KB smem + reg cap -> 2 CTAs per SM: one CTA's
// prologue/epilogue overlaps the other's tensor mainloop.
__global__ void __launch_bounds__(256, 2)
gemm_kernel(const float* __restrict__ b1)
{
    extern __shared__ char smem[];
    uint32_t tiles = smem_u32(smem);
    const int tid  = threadIdx.x;
    const int lane = tid & 31;
    const int w    = tid >> 5;
    const int wm   = w >> 2;          // 0..1  (64-row warp band)
    const int wn   = w & 3;           // 0..3  (32-col warp band)
    const int bx = blockIdx.x, by = blockIdx.y;
    const int row0 = by * BM, col0 = bx * BN;

    float acc[4][4][4];
    #pragma unroll
    for (int mt = 0; mt < 4; ++mt)
        #pragma unroll
        for (int nt = 0; nt < 4; ++nt)
            #pragma unroll
            for (int v = 0; v < 4; ++v) acc[mt][nt][v] = 0.f;

    // prologue: stages 0,1
    #pragma unroll
    for (int s = 0; s < 2; ++s) { load_stage(tiles + s * STAGE_BYTES, row0, col0, s * BK, tid); CP_COMMIT(); }

    // lane-invariant ldmatrix address components
    const uint32_t aOff = (wm * 64 + (lane & 15)) * ROWB + (lane >> 4) * 16;
    const uint32_t bOff = ASTAGE + (wn * 32 + ((lane & 7) + ((lane >> 4) << 3))) * ROWB
                        + ((lane >> 3) & 1) * 16;

    for (int j = 0; j < NKITER; ++j) {
        if (j < NKITER - 1) { CP_WAIT1(); } else { CP_WAIT0(); }
        __syncthreads();                    // single barrier per iteration
        if (j + 2 < NKITER) {
            // stage (j+2)%3 == (j-1)%3; safe: the barrier above proves all
            // threads finished iter j-1's ldsm reads of that stage.
            load_stage(tiles + ((j + 2) % STAGES) * STAGE_BYTES, row0, col0, (j + 2) * BK, tid);
            CP_COMMIT();
        }
        uint32_t st = tiles + (j % STAGES) * STAGE_BYTES;
        uint32_t aB = st + aOff;
        uint32_t bB = st + bOff;
        #pragma unroll
        for (int kk = 0; kk < 2; ++kk) {
            uint32_t a[4][4], b[2][4];
            #pragma unroll
            for (int mt = 0; mt < 4; ++mt) ldsm4(a[mt], aB + mt * 16 * ROWB + kk * 32);
            #pragma unroll
            for (int p = 0; p < 2; ++p)    ldsm4(b[p], bB + p * 16 * ROWB + kk * 32);
            #pragma unroll
            for (int mt = 0; mt < 4; ++mt)
                #pragma unroll
                for (int nt = 0; nt < 4; ++nt)
                    mma16816(acc[mt][nt], a[mt], &b[nt >> 1][(nt & 1) * 2]);
        }
    }

    // ---- epilogue: +b1, per-row top-2 over this 128-col tile ----
    float bv[8];
    #pragma unroll
    for (int nt = 0; nt < 4; ++nt) {
        int c = col0 + wn * 32 + nt * 8 + (lane & 3) * 2;
        bv[nt * 2]     = __ldg(&b1[c]);
        bv[nt * 2 + 1] = __ldg(&b1[c + 1]);
    }
    float* sv = (float*)smem;                       // [128][4][2]
    int*   si = (int*)(smem + 4096);                // [128][4][2]

    #pragma unroll
    for (int mt = 0; mt < 4; ++mt)
        #pragma unroll
        for (int h = 0; h < 2; ++h) {
            float v1 = -3e38f, v2 = -3e38f;
            int   i1 = 0x7fffffff, i2 = 0x7fffffff;
            #pragma unroll
            for (int nt = 0; nt < 4; ++nt)
                #pragma unroll
                for (int e = 0; e < 2; ++e) {
                    float v = acc[mt][nt][h * 2 + e] + bv[nt * 2 + e];
                    int col = col0 + wn * 32 + nt * 8 + (lane & 3) * 2 + e;
                    top2_merge(v1, i1, v2, i2, v, col);
                }
            #pragma unroll
            for (int off = 1; off <= 2; off <<= 1) {
                float ov1 = __shfl_xor_sync(~0u, v1, off);
                int   oi1 = __shfl_xor_sync(~0u, i1, off);
                float ov2 = __shfl_xor_sync(~0u, v2, off);
                int   oi2 = __shfl_xor_sync(~0u, i2, off);
                top2_merge(v1, i1, v2, i2, ov1, oi1);
                top2_merge(v1, i1, v2, i2, ov2, oi2);
            }
            if ((lane & 3) == 0) {
                int rl = wm * 64 + mt * 16 + h * 8 + (lane >> 2);
                sv[(rl * 4 + wn) * 2]     = v1;
                sv[(rl * 4 + wn) * 2 + 1] = v2;
                si[(rl * 4 + wn) * 2]     = i1;
                si[(rl * 4 + wn) * 2 + 1] = i2;
            }
        }
    __syncthreads();
    if (tid < 128) {
        float v1 = -3e38f, v2 = -3e38f;
        int   i1 = 0x7fffffff, i2 = 0x7fffffff;
        #pragma unroll
        for (int k = 0; k < 8; ++k)
            top2_merge(v1, i1, v2, i2, sv[tid * 8 + k], si[tid * 8 + k]);
        size_t o = (size_t)(row0 + tid) * (NTILEC * 2) + bx * 2;
        g_t2v[o] = v1; g_t2i[o] = i1;
        g_t2v[o + 1] = v2; g_t2i[o + 1] = i2;
    }
}

// ---------------- exact refinement: sequential fp32 FMA chain -----
// Fast path: if only ONE column lies within DELTA of the bf16 max, the
// bf16 top-1 is provably the fp32 argmax -> skip the chain (~87% of rows).
__global__ void __launch_bounds__(256)
refine_kernel(const float* __restrict__ x, const float* __restrict__ w1,
              const float* __restrict__ b1)
{
    __shared__ int s_cand[8][32];
    const int w = threadIdx.x >> 5, lane = threadIdx.x & 31;
    const int row = blockIdx.x * 8 + w;

    float v0 = g_t2v[(size_t)row * 64 + lane];
    float v1 = g_t2v[(size_t)row * 64 + 32 + lane];
    int   c0 = g_t2i[(size_t)row * 64 + lane];
    int   c1 = g_t2i[(size_t)row * 64 + 32 + lane];
    float m = fmaxf(v0, v1);
    #pragma unroll
    for (int o = 16; o; o >>= 1) m = fmaxf(m, __shfl_xor_sync(~0u, m, o));
    unsigned mask0 = __ballot_sync(~0u, v0 >= m - DELTA);
    unsigned mask1 = __ballot_sync(~0u, v1 >= m - DELTA);
    int n0 = __popc(mask0);
    int nc = n0 + __popc(mask1);
    if (nc > 32) nc = 32;
    if ((mask0 >> lane) & 1)
        s_cand[w][__popc(mask0 & ((1u << lane) - 1))] = c0;
    if ((mask1 >> lane) & 1) {
        int sl = n0 + __popc(mask1 & ((1u << lane) - 1));
        if (sl < 32) s_cand[w][sl] = c1;
    }
    __syncwarp();

    if (nc == 1) {                      // unique candidate == argmax; no chain
        if (lane == 0) g_amax[row] = s_cand[w][0];
        return;
    }

    const bool act = lane < nc;
    int j = s_cand[w][act ? lane : 0];
    const float* xr = x + (size_t)row * NFEAT;
    const float* wr = w1 + (size_t)j * NFEAT;

    float s = 0.f;
    #pragma unroll 4
    for (int k = 0; k < NFEAT; k += 8) {
        float4 xa = *(const float4*)&xr[k];
        float4 xb = *(const float4*)&xr[k + 4];
        float4 wa = *(const float4*)&wr[k];
        float4 wb = *(const float4*)&wr[k + 4];
        ffma_rn(s, xa.x, wa.x); ffma_rn(s, xa.y, wa.y);
        ffma_rn(s, xa.z, wa.z); ffma_rn(s, xa.w, wa.w);
        ffma_rn(s, xb.x, wb.x); ffma_rn(s, xb.y, wb.y);
        ffma_rn(s, xb.z, wb.z); ffma_rn(s, xb.w, wb.w);
    }
    float bb = __ldg(&b1[j]);
    asm("add.rn.f32 %0, %0, %1;" : "+f"(s) : "f"(bb));

    if (!act) { s = -3e38f; j = 0x7fffffff; }
    #pragma unroll
    for (int o = 16; o; o >>= 1) {
        float os = __shfl_xor_sync(~0u, s, o);
        int   oj = __shfl_xor_sync(~0u, j, o);
        if (os > s || (os == s && oj < j)) { s = os; j = oj; }
    }
    if (lane == 0) g_amax[row] = j;
}

// ---------------- transpose w2 [1000,4096] -> [4096,1000] ---------
__global__ void transpose_kernel(const float* __restrict__ w2)
{
    __shared__ float tile[32][33];
    const int bx = blockIdx.x, by = blockIdx.y;
    const int tx = threadIdx.x, ty = threadIdx.y;
    const int c = bx * 32 + tx;
    #pragma unroll
    for (int j = 0; j < 32; j += 8) {
        int r = by * 32 + ty + j;
        if (r < NCLS) tile[ty + j][tx] = w2[(size_t)r * NINT + c];
    }
    __syncthreads();
    const int oc = by * 32 + tx;
    #pragma unroll
    for (int j = 0; j < 32; j += 8) {
        int orow = bx * 32 + ty + j;
        if (oc < NCLS) g_w2t[(size_t)orow * NCLS + oc] = tile[tx][ty + j];
    }
}

// ---------------- gather: out[b,:] = w2t[idx[b],:] + b2 -----------
__global__ void gather_kernel(const float* __restrict__ b2, float* __restrict__ out)
{
    const int b = blockIdx.x;
    const int idx = g_amax[b];
    const float4* src = (const float4*)&g_w2t[(size_t)idx * NCLS];
    const float4* bb  = (const float4*)b2;
    float4* dst = (float4*)&out[(size_t)b * NCLS];
    const int t = threadIdx.x;
    if (t < NCLS / 4) {
        float4 v = src[t], w = bb[t];
        v.x += w.x; v.y += w.y; v.z += w.z; v.w += w.w;
        dst[t] = v;
    }
}

// ------------------------------------------------------------------
extern "C" void kernel_launch(void* const* d_in, const int* in_sizes, int n_in,
                              void* d_out, int out_size)
{
    const float* x  = (const float*)d_in[0];
    const float* w1 = (const float*)d_in[1];
    const float* b1 = (const float*)d_in[2];
    const float* w2 = (const float*)d_in[3];
    const float* b2 = (const float*)d_in[4];
    float* out = (float*)d_out;

    cudaFuncSetAttribute(gemm_kernel, cudaFuncAttributeMaxDynamicSharedMemorySize, SMEM_DYN);

    const int cvt_blocks = (int)(((size_t)B_ROWS * NFEAT / 8 + (size_t)NINT * NFEAT / 8 + 255) / 256);
    cvt_kernel<<<cvt_blocks, 256>>>((const float4*)x, (const float4*)w1);
    gemm_kernel<<<dim3(NTILEC, B_ROWS / BM), 256, SMEM_DYN>>>(b1);
    refine_kernel<<<B_ROWS / 8, 256>>>(x, w1, b1);
    transpose_kernel<<<dim3(NINT / 32, (NCLS + 31) / 32), dim3(32, 8)>>>(w2);
    gather_kernel<<<B_ROWS, 256>>>(b2, out);
}